// round 1
// baseline (speedup 1.0000x reference)
#include <cuda_runtime.h>
#include <cstddef>

// Problem constants (fixed by the dataset): B=2, T=1024, C=256, head_dim=2, H=128
#define BB 2
#define TT 1024
#define CC 256
#define HH 128

// Scratch (no allocations allowed -> __device__ globals)
__device__ float  g_qkv[BB * TT * 3 * CC];        // (2048, 768)
__device__ float2 g_q  [BB * HH * TT];            // per (b,h,t): normalized q * (log2e/sqrt2) * qn_w
__device__ float4 g_kv [BB * HH * TT];            // per (b,h,s): (kn0, kn1, v0, v1)
__device__ float  g_y  [BB * TT * CC];            // attention output in (b,t,c) layout

__device__ __forceinline__ float ex2f(float x) {
    float r;
    asm("ex2.approx.f32 %0, %1;" : "=f"(r) : "f"(x));
    return r;
}

// ---------------------------------------------------------------------------
// C[m][n] = sum_k A[m*K+k] * W[n*K+k]   (both K-contiguous; M,N%64==0, K%16==0)
// 64x64 tile, 16x16 threads, 4x4 microtile.
// ---------------------------------------------------------------------------
__global__ void sgemm_nt(const float* __restrict__ A, const float* __restrict__ W,
                         float* __restrict__ Cout, int M, int N, int K)
{
    __shared__ float As[16][64];
    __shared__ float Ws[16][64];
    const int tx = threadIdx.x, ty = threadIdx.y;
    const int tid = ty * 16 + tx;
    const int m0 = blockIdx.y * 64, n0 = blockIdx.x * 64;
    const int row = tid >> 2;          // 0..63
    const int kq  = (tid & 3) * 4;     // 0,4,8,12

    float acc[4][4] = {};

    for (int k0 = 0; k0 < K; k0 += 16) {
        float4 av = *(const float4*)(A + (size_t)(m0 + row) * K + k0 + kq);
        float4 wv = *(const float4*)(W + (size_t)(n0 + row) * K + k0 + kq);
        __syncthreads();
        As[kq + 0][row] = av.x; As[kq + 1][row] = av.y;
        As[kq + 2][row] = av.z; As[kq + 3][row] = av.w;
        Ws[kq + 0][row] = wv.x; Ws[kq + 1][row] = wv.y;
        Ws[kq + 2][row] = wv.z; Ws[kq + 3][row] = wv.w;
        __syncthreads();
        #pragma unroll
        for (int k = 0; k < 16; k++) {
            float4 a = *(const float4*)&As[k][ty * 4];
            float4 b = *(const float4*)&Ws[k][tx * 4];
            float ar[4] = {a.x, a.y, a.z, a.w};
            float br[4] = {b.x, b.y, b.z, b.w};
            #pragma unroll
            for (int i = 0; i < 4; i++)
                #pragma unroll
                for (int j = 0; j < 4; j++)
                    acc[i][j] = fmaf(ar[i], br[j], acc[i][j]);
        }
    }
    #pragma unroll
    for (int i = 0; i < 4; i++) {
        float4 v = make_float4(acc[i][0], acc[i][1], acc[i][2], acc[i][3]);
        *(float4*)(Cout + (size_t)(m0 + ty * 4 + i) * N + n0 + tx * 4) = v;
    }
}

// ---------------------------------------------------------------------------
// Split qkv + RMSNorm(q,k) over head_dim=2, fold softmax scale*log2e into q,
// repack into per-(b,h) contiguous layouts for the attention kernel.
// ---------------------------------------------------------------------------
__global__ void split_norm(const float* __restrict__ qn_w, const float* __restrict__ kn_w)
{
    int i = blockIdx.x * blockDim.x + threadIdx.x;
    if (i >= BB * HH * TT) return;
    int t = i % TT;
    int h = (i / TT) % HH;
    int b = i / (HH * TT);

    const float* rowp = g_qkv + (size_t)(b * TT + t) * (3 * CC);
    float2 q = *(const float2*)(rowp + 2 * h);
    float2 k = *(const float2*)(rowp + CC + 2 * h);
    float2 v = *(const float2*)(rowp + 2 * CC + 2 * h);

    // log2(e)/sqrt(2): fold softmax scale and base-2 exp conversion into q
    const float L2SCALE = 1.02013946f;
    float rq = rsqrtf(0.5f * (q.x * q.x + q.y * q.y) + 1e-6f);
    float rk = rsqrtf(0.5f * (k.x * k.x + k.y * k.y) + 1e-6f);

    float2 qs = make_float2(q.x * rq * qn_w[0] * L2SCALE,
                            q.y * rq * qn_w[1] * L2SCALE);
    float4 kv = make_float4(k.x * rk * kn_w[0], k.y * rk * kn_w[1], v.x, v.y);

    size_t o = (size_t)(b * HH + h) * TT + t;
    g_q[o]  = qs;
    g_kv[o] = kv;
}

// ---------------------------------------------------------------------------
// Causal attention, head_dim=2. One block per (b*h, 128-row t tile).
// Logits bounded in [-sqrt2, sqrt2] -> no max subtraction needed; exp via ex2.
// ---------------------------------------------------------------------------
__global__ void __launch_bounds__(128) attn_kernel()
{
    __shared__ float4 skv[TT];
    const int bh = blockIdx.x;
    const int t0 = blockIdx.y * 128;
    const float4* kvp = g_kv + (size_t)bh * TT;
    const int s_end = t0 + 128;

    for (int i = threadIdx.x; i < s_end; i += 128) skv[i] = kvp[i];
    __syncthreads();

    const int t = t0 + threadIdx.x;
    const float2 q = g_q[(size_t)bh * TT + t];

    float n0[4] = {0.f, 0.f, 0.f, 0.f};
    float n1[4] = {0.f, 0.f, 0.f, 0.f};
    float dd[4] = {0.f, 0.f, 0.f, 0.f};

    const int n  = t + 1;
    const int n4 = n & ~3;
    int s = 0;
    for (; s < n4; s += 4) {
        #pragma unroll
        for (int j = 0; j < 4; j++) {
            float4 kv = skv[s + j];
            float p = ex2f(fmaf(q.x, kv.x, q.y * kv.y));
            n0[j] = fmaf(p, kv.z, n0[j]);
            n1[j] = fmaf(p, kv.w, n1[j]);
            dd[j] += p;
        }
    }
    for (; s < n; ++s) {
        float4 kv = skv[s];
        float p = ex2f(fmaf(q.x, kv.x, q.y * kv.y));
        n0[0] = fmaf(p, kv.z, n0[0]);
        n1[0] = fmaf(p, kv.w, n1[0]);
        dd[0] += p;
    }

    float num0 = (n0[0] + n0[1]) + (n0[2] + n0[3]);
    float num1 = (n1[0] + n1[1]) + (n1[2] + n1[3]);
    float den  = (dd[0] + dd[1]) + (dd[2] + dd[3]);
    float inv  = 1.0f / den;

    const int b = bh >> 7;       // / HH
    const int h = bh & 127;      // % HH
    float* yp = g_y + (size_t)(b * TT + t) * CC + 2 * h;
    yp[0] = num0 * inv;
    yp[1] = num1 * inv;
}

// ---------------------------------------------------------------------------
extern "C" void kernel_launch(void* const* d_in, const int* in_sizes, int n_in,
                              void* d_out, int out_size)
{
    const float* x      = (const float*)d_in[0];   // (2,1024,256)
    const float* w_qkv  = (const float*)d_in[1];   // (768,256)
    const float* w_proj = (const float*)d_in[2];   // (256,256)
    const float* qn_w   = (const float*)d_in[3];   // (2,)
    const float* kn_w   = (const float*)d_in[4];   // (2,)
    float* out = (float*)d_out;                    // (2,1024,256)

    float *qkv_p, *y_p;
    cudaGetSymbolAddress((void**)&qkv_p, g_qkv);
    cudaGetSymbolAddress((void**)&y_p,   g_y);

    dim3 blk(16, 16);
    // qkv = x @ w_qkv^T : (2048,768)
    sgemm_nt<<<dim3(768 / 64, 2048 / 64), blk>>>(x, w_qkv, qkv_p, BB * TT, 3 * CC, CC);
    // rmsnorm + repack
    split_norm<<<(BB * HH * TT) / 256, 256>>>(qn_w, kn_w);
    // causal attention
    attn_kernel<<<dim3(BB * HH, TT / 128), 128>>>();
    // out = y @ w_proj^T : (2048,256)
    sgemm_nt<<<dim3(256 / 64, 2048 / 64), blk>>>(y_p, w_proj, out, BB * TT, CC, CC);
}